// round 12
// baseline (speedup 1.0000x reference)
#include <cuda_runtime.h>

// moving_image [1,1,192,192,192] f32, vector_field [1,3,192,192,192] f32,
// fixed_image [1,1,192,192,192] f32, fixed_image_mask (uint8/int32/float32, runtime-detected).
// Output scalar f32 = sum((warp(mov,vf)-fixed)^2 * mask) / max(sum(mask),1).

#define DD 192
#define HH 192
#define WW 192
#define NVOX (DD * HH * WW)

#define THREADS 256                       // 8 warps; 1 warp = 1 row
#define ROWS_PER_BLK 8
#define NBLK ((DD * HH) / ROWS_PER_BLK)   // 4608
#define PITER 3                           // 3 iters, each lane does an x-pair: x = 2*lane + 64*j

__device__ float g_part_sq[NBLK];
__device__ float g_part_m[NBLK];
__device__ unsigned int g_done = 0;       // reset by last block each run -> replay-safe

__device__ __forceinline__ float sample_zero_pad(const float* __restrict__ mov,
                                                 int iz, int iy, int ix) {
    if ((unsigned)iz >= DD || (unsigned)iy >= HH || (unsigned)ix >= WW) return 0.0f;
    return __ldg(mov + (iz * HH + iy) * WW + ix);
}

__device__ __forceinline__ float trilerp(const float* __restrict__ mov,
                                         float zz, float yy, float xx) {
    int z0 = __float2int_rd(zz);
    int y0 = __float2int_rd(yy);
    int x0 = __float2int_rd(xx);
    float wz = zz - (float)z0;
    float wy = yy - (float)y0;
    float wx = xx - (float)x0;
    float wz0 = 1.0f - wz, wy0 = 1.0f - wy, wx0 = 1.0f - wx;

    if ((unsigned)z0 <= DD - 2 && (unsigned)y0 <= HH - 2 && (unsigned)x0 <= WW - 2) {
        // Interior fast path: 8 direct scalar gathers (proven optimal form).
        const float* p = mov + ((z0 * HH + y0) * WW + x0);
        float c000 = __ldg(p);
        float c001 = __ldg(p + 1);
        float c010 = __ldg(p + WW);
        float c011 = __ldg(p + WW + 1);
        const float* q = p + HH * WW;
        float c100 = __ldg(q);
        float c101 = __ldg(q + 1);
        float c110 = __ldg(q + WW);
        float c111 = __ldg(q + WW + 1);
        return wz0 * (wy0 * (wx0 * c000 + wx * c001) +
                      wy  * (wx0 * c010 + wx * c011)) +
               wz  * (wy0 * (wx0 * c100 + wx * c101) +
                      wy  * (wx0 * c110 + wx * c111));
    } else {
        int z1 = z0 + 1, y1 = y0 + 1, x1 = x0 + 1;
        float c000 = sample_zero_pad(mov, z0, y0, x0);
        float c001 = sample_zero_pad(mov, z0, y0, x1);
        float c010 = sample_zero_pad(mov, z0, y1, x0);
        float c011 = sample_zero_pad(mov, z0, y1, x1);
        float c100 = sample_zero_pad(mov, z1, y0, x0);
        float c101 = sample_zero_pad(mov, z1, y0, x1);
        float c110 = sample_zero_pad(mov, z1, y1, x0);
        float c111 = sample_zero_pad(mov, z1, y1, x1);
        return wz0 * (wy0 * (wx0 * c000 + wx * c001) +
                      wy  * (wx0 * c010 + wx * c011)) +
               wz  * (wy0 * (wx0 * c100 + wx * c101) +
                      wy  * (wx0 * c110 + wx * c111));
    }
}

__global__ __launch_bounds__(THREADS) void warp_mse_kernel(
    const float* __restrict__ mov,
    const float* __restrict__ vf,
    const float* __restrict__ fix,
    const void* __restrict__ mask_raw,
    float* __restrict__ out) {

    __shared__ int sh_mode;
    __shared__ bool sh_last;

    const int tid = threadIdx.x;
    const int lane = tid & 31;
    const int wid = tid >> 5;

    // Per-block mask encoding detection from the first 256 bytes (L1/L2-resident).
    //  - float32 0/1: byte 0x3f at pos%4==3 or 0x80 at pos%4==2 -> mode 2
    //  - int32 0/1: all bytes at pos%4!=0 zero -> mode 1
    //  - uint8 0/1: nonzero byte at pos%4!=0 (P[miss] ~ 2^-192) -> mode 0
    if (wid == 0) {
        const unsigned char* mb = (const unsigned char*)mask_raw;
        int f32 = 0, mis = 0;
#pragma unroll
        for (int k = 0; k < 8; k++) {
            int pos = lane * 8 + k;
            unsigned char b = __ldg(mb + pos);
            int off = pos & 3;
            if (off == 3 && b == 0x3f) f32 = 1;
            if (off == 2 && b == 0x80) f32 = 1;
            if (off != 0 && b != 0) mis = 1;
        }
        unsigned f32b = __ballot_sync(0xffffffffu, f32);
        unsigned misb = __ballot_sync(0xffffffffu, mis);
        if (lane == 0) sh_mode = f32b ? 2 : (misb ? 0 : 1);
    }
    __syncthreads();
    const int mask_mode = sh_mode;

    const int row = blockIdx.x * ROWS_PER_BLK + wid;
    const int y = row % HH;
    const int z = row / HH;
    const int rowbase = row * WW;
    const float zf = (float)z;
    const float yf = (float)y;

    float s_sq = 0.0f;
    float s_m = 0.0f;

    // Each lane owns x-pairs: x = 2*lane + 64*j (8B-aligned -> 64-bit streaming loads).
#pragma unroll
    for (int j = 0; j < PITER; j++) {
        const int x = 2 * lane + 64 * j;
        const int idx = rowbase + x;

        float2 dz2 = __ldg((const float2*)(vf + idx));
        float2 dy2 = __ldg((const float2*)(vf + idx + NVOX));
        float2 dx2 = __ldg((const float2*)(vf + idx + 2 * NVOX));
        float2 f2 = __ldg((const float2*)(fix + idx));

        float mA, mB;
        if (mask_mode == 1) {
            int2 mi = __ldg((const int2*)((const int*)mask_raw + idx));
            mA = (float)mi.x; mB = (float)mi.y;
        } else if (mask_mode == 2) {
            float2 mf = __ldg((const float2*)((const float*)mask_raw + idx));
            mA = mf.x; mB = mf.y;
        } else {
            unsigned short mp = __ldg((const unsigned short*)((const unsigned char*)mask_raw + idx));
            mA = (float)(mp & 0xff); mB = (float)(mp >> 8);
        }

        // Masked-out voxels contribute exactly 0 -> skip their 8 gathers entirely.
        // Predicated-off lanes issue no memory requests -> fewer L1tex wavefronts.
        if (mA != 0.0f) {
            float wA = trilerp(mov, zf + dz2.x, yf + dy2.x, (float)x + dx2.x);
            float dA = wA - f2.x;
            s_sq = fmaf(dA * dA, mA, s_sq);
        }
        if (mB != 0.0f) {
            float wB = trilerp(mov, zf + dz2.y, yf + dy2.y, (float)(x + 1) + dx2.y);
            float dB = wB - f2.y;
            s_sq = fmaf(dB * dB, mB, s_sq);
        }
        s_m += mA + mB;
    }

    // Deterministic block tree reduction.
    __shared__ float sh_sq[THREADS];
    __shared__ float sh_m[THREADS];
    sh_sq[tid] = s_sq;
    sh_m[tid] = s_m;
    __syncthreads();
    for (int off = THREADS / 2; off > 0; off >>= 1) {
        if (tid < off) {
            sh_sq[tid] += sh_sq[tid + off];
            sh_m[tid] += sh_m[tid + off];
        }
        __syncthreads();
    }
    if (tid == 0) {
        g_part_sq[blockIdx.x] = sh_sq[0];
        g_part_m[blockIdx.x] = sh_m[0];
        __threadfence();
        unsigned int t = atomicAdd(&g_done, 1u);
        sh_last = (t == (unsigned)(NBLK - 1));
    }
    __syncthreads();

    // Last block reduces all partials (fixed index order -> deterministic).
    if (sh_last) {
        float t_sq = 0.0f, t_m = 0.0f;
        for (int i = tid; i < NBLK; i += THREADS) {
            t_sq += g_part_sq[i];
            t_m += g_part_m[i];
        }
        sh_sq[tid] = t_sq;
        sh_m[tid] = t_m;
        __syncthreads();
        for (int off = THREADS / 2; off > 0; off >>= 1) {
            if (tid < off) {
                sh_sq[tid] += sh_sq[tid + off];
                sh_m[tid] += sh_m[tid + off];
            }
            __syncthreads();
        }
        if (tid == 0) {
            out[0] = sh_sq[0] / fmaxf(sh_m[0], 1.0f);
            g_done = 0;  // reset for next graph replay
        }
    }
}

extern "C" void kernel_launch(void* const* d_in, const int* in_sizes, int n_in,
                              void* d_out, int out_size) {
    const float* mov = (const float*)d_in[0];
    const float* vf = (const float*)d_in[1];
    const float* fix = (const float*)d_in[2];
    const void* mask = d_in[3];
    float* out = (float*)d_out;

    warp_mse_kernel<<<NBLK, THREADS>>>(mov, vf, fix, mask, out);
}

// round 14
// speedup vs baseline: 1.1463x; 1.1463x over previous
#include <cuda_runtime.h>

// moving_image [1,1,192,192,192] f32, vector_field [1,3,192,192,192] f32,
// fixed_image [1,1,192,192,192] f32, fixed_image_mask (uint8/int32/float32, runtime-detected).
// Output scalar f32 = sum((warp(mov,vf)-fixed)^2 * mask) / max(sum(mask),1).

#define DD 192
#define HH 192
#define WW 192
#define NVOX (DD * HH * WW)

#define THREADS 256                       // 8 warps; 1 warp = 1 row
#define ROWS_PER_BLK 8
#define NBLK ((DD * HH) / ROWS_PER_BLK)   // 4608
#define PITER 3                           // 3 iters, each lane does an x-pair: x = 2*lane + 64*j

#define FIN_THREADS 512

__device__ float g_part_sq[NBLK];
__device__ float g_part_m[NBLK];

__device__ __forceinline__ float sample_zero_pad(const float* __restrict__ mov,
                                                 int iz, int iy, int ix) {
    if ((unsigned)iz >= DD || (unsigned)iy >= HH || (unsigned)ix >= WW) return 0.0f;
    return __ldg(mov + (iz * HH + iy) * WW + ix);
}

__device__ __forceinline__ float trilerp(const float* __restrict__ mov,
                                         float zz, float yy, float xx) {
    int z0 = __float2int_rd(zz);
    int y0 = __float2int_rd(yy);
    int x0 = __float2int_rd(xx);
    float wz = zz - (float)z0;
    float wy = yy - (float)y0;
    float wx = xx - (float)x0;
    float wz0 = 1.0f - wz, wy0 = 1.0f - wy, wx0 = 1.0f - wx;

    if ((unsigned)z0 <= DD - 2 && (unsigned)y0 <= HH - 2 && (unsigned)x0 <= WW - 2) {
        // Interior fast path: 8 direct scalar gathers (proven optimal form).
        const float* p = mov + ((z0 * HH + y0) * WW + x0);
        float c000 = __ldg(p);
        float c001 = __ldg(p + 1);
        float c010 = __ldg(p + WW);
        float c011 = __ldg(p + WW + 1);
        const float* q = p + HH * WW;
        float c100 = __ldg(q);
        float c101 = __ldg(q + 1);
        float c110 = __ldg(q + WW);
        float c111 = __ldg(q + WW + 1);
        return wz0 * (wy0 * (wx0 * c000 + wx * c001) +
                      wy  * (wx0 * c010 + wx * c011)) +
               wz  * (wy0 * (wx0 * c100 + wx * c101) +
                      wy  * (wx0 * c110 + wx * c111));
    } else {
        int z1 = z0 + 1, y1 = y0 + 1, x1 = x0 + 1;
        float c000 = sample_zero_pad(mov, z0, y0, x0);
        float c001 = sample_zero_pad(mov, z0, y0, x1);
        float c010 = sample_zero_pad(mov, z0, y1, x0);
        float c011 = sample_zero_pad(mov, z0, y1, x1);
        float c100 = sample_zero_pad(mov, z1, y0, x0);
        float c101 = sample_zero_pad(mov, z1, y0, x1);
        float c110 = sample_zero_pad(mov, z1, y1, x0);
        float c111 = sample_zero_pad(mov, z1, y1, x1);
        return wz0 * (wy0 * (wx0 * c000 + wx * c001) +
                      wy  * (wx0 * c010 + wx * c011)) +
               wz  * (wy0 * (wx0 * c100 + wx * c101) +
                      wy  * (wx0 * c110 + wx * c111));
    }
}

__global__ __launch_bounds__(THREADS) void warp_mse_kernel(
    const float* __restrict__ mov,
    const float* __restrict__ vf,
    const float* __restrict__ fix,
    const void* __restrict__ mask_raw) {

    __shared__ int sh_mode;

    const int tid = threadIdx.x;
    const int lane = tid & 31;
    const int wid = tid >> 5;

    // Per-block mask encoding detection from the first 256 bytes (L1/L2-resident).
    //  - float32 0/1: byte 0x3f at pos%4==3 or 0x80 at pos%4==2 -> mode 2
    //  - int32 0/1: all bytes at pos%4!=0 zero -> mode 1
    //  - uint8 0/1: nonzero byte at pos%4!=0 (P[miss] ~ 2^-192) -> mode 0
    if (wid == 0) {
        const unsigned char* mb = (const unsigned char*)mask_raw;
        int f32 = 0, mis = 0;
#pragma unroll
        for (int k = 0; k < 8; k++) {
            int pos = lane * 8 + k;
            unsigned char b = __ldg(mb + pos);
            int off = pos & 3;
            if (off == 3 && b == 0x3f) f32 = 1;
            if (off == 2 && b == 0x80) f32 = 1;
            if (off != 0 && b != 0) mis = 1;
        }
        unsigned f32b = __ballot_sync(0xffffffffu, f32);
        unsigned misb = __ballot_sync(0xffffffffu, mis);
        if (lane == 0) sh_mode = f32b ? 2 : (misb ? 0 : 1);
    }
    __syncthreads();
    const int mask_mode = sh_mode;

    const int row = blockIdx.x * ROWS_PER_BLK + wid;
    const int y = row % HH;
    const int z = row / HH;
    const int rowbase = row * WW;
    const float zf = (float)z;
    const float yf = (float)y;

    float s_sq = 0.0f;
    float s_m = 0.0f;

    // Each lane owns x-pairs: x = 2*lane + 64*j (8B-aligned -> 64-bit streaming loads).
#pragma unroll
    for (int j = 0; j < PITER; j++) {
        const int x = 2 * lane + 64 * j;
        const int idx = rowbase + x;

        float2 dz2 = __ldg((const float2*)(vf + idx));
        float2 dy2 = __ldg((const float2*)(vf + idx + NVOX));
        float2 dx2 = __ldg((const float2*)(vf + idx + 2 * NVOX));
        float2 f2 = __ldg((const float2*)(fix + idx));

        float mA, mB;
        if (mask_mode == 1) {
            int2 mi = __ldg((const int2*)((const int*)mask_raw + idx));
            mA = (float)mi.x; mB = (float)mi.y;
        } else if (mask_mode == 2) {
            float2 mf = __ldg((const float2*)((const float*)mask_raw + idx));
            mA = mf.x; mB = mf.y;
        } else {
            unsigned short mp = __ldg((const unsigned short*)((const unsigned char*)mask_raw + idx));
            mA = (float)(mp & 0xff); mB = (float)(mp >> 8);
        }

        // Masked-out voxels contribute exactly 0 -> skip their 8 gathers entirely.
        // Predicated-off lanes issue no memory requests -> fewer L1tex wavefronts.
        if (mA != 0.0f) {
            float wA = trilerp(mov, zf + dz2.x, yf + dy2.x, (float)x + dx2.x);
            float dA = wA - f2.x;
            s_sq = fmaf(dA * dA, mA, s_sq);
        }
        if (mB != 0.0f) {
            float wB = trilerp(mov, zf + dz2.y, yf + dy2.y, (float)(x + 1) + dx2.y);
            float dB = wB - f2.y;
            s_sq = fmaf(dB * dB, mB, s_sq);
        }
        s_m += mA + mB;
    }

    // Deterministic block tree reduction.
    __shared__ float sh_sq[THREADS];
    __shared__ float sh_m[THREADS];
    sh_sq[tid] = s_sq;
    sh_m[tid] = s_m;
    __syncthreads();
    for (int off = THREADS / 2; off > 0; off >>= 1) {
        if (tid < off) {
            sh_sq[tid] += sh_sq[tid + off];
            sh_m[tid] += sh_m[tid + off];
        }
        __syncthreads();
    }
    if (tid == 0) {
        g_part_sq[blockIdx.x] = sh_sq[0];
        g_part_m[blockIdx.x] = sh_m[0];
    }
}

__global__ __launch_bounds__(FIN_THREADS) void finalize_kernel(float* __restrict__ out) {
#if __CUDA_ARCH__ >= 900
    // PDL: this grid may be resident before the primary drains; wait for it.
    cudaGridDependencySynchronize();
#endif
    __shared__ float sh_sq[FIN_THREADS];
    __shared__ float sh_m[FIN_THREADS];
    int tid = threadIdx.x;
    float s_sq = 0.0f, s_m = 0.0f;
#pragma unroll
    for (int i = tid; i < NBLK; i += FIN_THREADS) {
        s_sq += __ldg(&g_part_sq[i]);
        s_m += __ldg(&g_part_m[i]);
    }
    sh_sq[tid] = s_sq;
    sh_m[tid] = s_m;
    __syncthreads();
    for (int off = FIN_THREADS / 2; off > 0; off >>= 1) {
        if (tid < off) {
            sh_sq[tid] += sh_sq[tid + off];
            sh_m[tid] += sh_m[tid + off];
        }
        __syncthreads();
    }
    if (tid == 0) {
        out[0] = sh_sq[0] / fmaxf(sh_m[0], 1.0f);
    }
}

extern "C" void kernel_launch(void* const* d_in, const int* in_sizes, int n_in,
                              void* d_out, int out_size) {
    const float* mov = (const float*)d_in[0];
    const float* vf = (const float*)d_in[1];
    const float* fix = (const float*)d_in[2];
    const void* mask = d_in[3];
    float* out = (float*)d_out;

    warp_mse_kernel<<<NBLK, THREADS>>>(mov, vf, fix, mask);

    // Finalize with programmatic dependent launch (overlap launch latency with
    // the primary's tail); fall back to a plain launch if unsupported.
    cudaLaunchConfig_t cfg = {};
    cfg.gridDim = dim3(1, 1, 1);
    cfg.blockDim = dim3(FIN_THREADS, 1, 1);
    cfg.dynamicSmemBytes = 0;
    cfg.stream = 0;
    cudaLaunchAttribute attrs[1];
    attrs[0].id = cudaLaunchAttributeProgrammaticStreamSerialization;
    attrs[0].val.programmaticStreamSerializationAllowed = 1;
    cfg.attrs = attrs;
    cfg.numAttrs = 1;
    cudaError_t e = cudaLaunchKernelEx(&cfg, finalize_kernel, out);
    if (e != cudaSuccess) {
        (void)cudaGetLastError();  // clear sticky error
        finalize_kernel<<<1, FIN_THREADS>>>(out);
    }
}